// round 3
// baseline (speedup 1.0000x reference)
#include <cuda_runtime.h>
#include <cstdint>

// 2x nearest-neighbor upsample, 256-bit loads/stores, 2 chunks per thread.
// in : [16, 64, 256, 256] fp32 = 67108864 floats
// out: [16, 64, 512, 512] fp32
//
// Each thread handles TWO 32-byte input chunks (idx and idx + n8half),
// issuing both 256-bit loads up front (MLP=2), then 8x 256-bit streaming
// stores. Input is read via the non-coherent (read-once) path; output is
// written with .cs (streaming / evict-first) policy.

static constexpr int W8_IN = 32;   // 8-float chunks per input row (256/8)
static constexpr int W_OUT = 512;  // floats per output row

__device__ __forceinline__ void load_v8(const float* p,
                                        float& f0, float& f1, float& f2, float& f3,
                                        float& f4, float& f5, float& f6, float& f7)
{
    asm volatile(
        "ld.global.nc.v8.f32 {%0,%1,%2,%3,%4,%5,%6,%7}, [%8];"
        : "=f"(f0), "=f"(f1), "=f"(f2), "=f"(f3),
          "=f"(f4), "=f"(f5), "=f"(f6), "=f"(f7)
        : "l"(p));
}

__device__ __forceinline__ void store_patch(float* op,
                                            float f0, float f1, float f2, float f3,
                                            float f4, float f5, float f6, float f7)
{
    // Row 0: [f0 f0 f1 f1 f2 f2 f3 f3][f4 f4 f5 f5 f6 f6 f7 f7], Row 1 = Row 0
    asm volatile(
        "st.global.cs.v8.f32 [%0], {%1,%2,%3,%4,%5,%6,%7,%8};"
        :: "l"(op),
           "f"(f0), "f"(f0), "f"(f1), "f"(f1),
           "f"(f2), "f"(f2), "f"(f3), "f"(f3) : "memory");
    asm volatile(
        "st.global.cs.v8.f32 [%0], {%1,%2,%3,%4,%5,%6,%7,%8};"
        :: "l"(op + 8),
           "f"(f4), "f"(f4), "f"(f5), "f"(f5),
           "f"(f6), "f"(f6), "f"(f7), "f"(f7) : "memory");
    asm volatile(
        "st.global.cs.v8.f32 [%0], {%1,%2,%3,%4,%5,%6,%7,%8};"
        :: "l"(op + W_OUT),
           "f"(f0), "f"(f0), "f"(f1), "f"(f1),
           "f"(f2), "f"(f2), "f"(f3), "f"(f3) : "memory");
    asm volatile(
        "st.global.cs.v8.f32 [%0], {%1,%2,%3,%4,%5,%6,%7,%8};"
        :: "l"(op + W_OUT + 8),
           "f"(f4), "f"(f4), "f"(f5), "f"(f5),
           "f"(f6), "f"(f6), "f"(f7), "f"(f7) : "memory");
}

__global__ __launch_bounds__(256)
void upsample2x_v8x2_kernel(const float* __restrict__ in,
                            float* __restrict__ out,
                            int n8half)
{
    int idx = blockIdx.x * blockDim.x + threadIdx.x;
    if (idx >= n8half) return;

    int idxA = idx;
    int idxB = idx + n8half;

    // Front-batched independent loads (MLP = 2)
    float a0,a1,a2,a3,a4,a5,a6,a7;
    float b0,b1,b2,b3,b4,b5,b6,b7;
    load_v8(in + (size_t)idxA * 8, a0,a1,a2,a3,a4,a5,a6,a7);
    load_v8(in + (size_t)idxB * 8, b0,b1,b2,b3,b4,b5,b6,b7);

    {
        int row  = idxA >> 5;
        int col8 = idxA & (W8_IN - 1);
        float* op = out + (size_t)(row * 2) * W_OUT + (size_t)col8 * 16;
        store_patch(op, a0,a1,a2,a3,a4,a5,a6,a7);
    }
    {
        int row  = idxB >> 5;
        int col8 = idxB & (W8_IN - 1);
        float* op = out + (size_t)(row * 2) * W_OUT + (size_t)col8 * 16;
        store_patch(op, b0,b1,b2,b3,b4,b5,b6,b7);
    }
}

extern "C" void kernel_launch(void* const* d_in, const int* in_sizes, int n_in,
                              void* d_out, int out_size)
{
    const float* in  = (const float*)d_in[0];
    float*       out = (float*)d_out;

    int n_elems = in_sizes[0];          // 67108864
    int n8      = n_elems / 8;          // 8388608 chunks
    int n8half  = n8 / 2;               // 4194304 threads

    int threads = 256;
    int blocks  = (n8half + threads - 1) / threads;
    upsample2x_v8x2_kernel<<<blocks, threads>>>(in, out, n8half);
}